// round 1
// baseline (speedup 1.0000x reference)
#include <cuda_runtime.h>
#include <cuda_bf16.h>

#define L_RES 512
#define C_S   256
#define C_Z   128
#define LN_EPS 1e-5f

// Scratch (no allocations allowed)
__device__ float g_u[L_RES * C_S];     // LayerNorm'd embeddings (512KB)
__device__ float g_zjb[L_RES * C_Z];   // u @ W2 + b_pair        (256KB)

// ---------------------------------------------------------------------------
// Kernel 1: gather + LayerNorm + zjb = u @ W2 + b_pair. One block per residue.
// ---------------------------------------------------------------------------
__global__ void prep_kernel(const int* __restrict__ seq,
                            const int* __restrict__ chain,
                            const int* __restrict__ ridx,
                            const float* __restrict__ E_aa,
                            const float* __restrict__ E_pos,
                            const float* __restrict__ E_chain,
                            const float* __restrict__ W_pair,
                            const float* __restrict__ b_pair,
                            const float* __restrict__ ln_w,
                            const float* __restrict__ ln_b,
                            float* __restrict__ out_s)
{
    int i = blockIdx.x;
    int t = threadIdx.x;            // 256 threads == C_S

    __shared__ float u_s[C_S];
    __shared__ float red[8];
    __shared__ float mu_sh, rstd_sh;

    int sq = seq[i], ci = chain[i], ri = ridx[i];
    float v = E_aa[sq * C_S + t] + E_pos[ri * C_S + t] + E_chain[ci * C_S + t];
    out_s[i * C_S + t] = v;

    // mean
    float x = v;
    #pragma unroll
    for (int o = 16; o; o >>= 1) x += __shfl_xor_sync(0xffffffffu, x, o);
    if ((t & 31) == 0) red[t >> 5] = x;
    __syncthreads();
    if (t == 0) {
        float s = 0.f;
        #pragma unroll
        for (int w = 0; w < 8; w++) s += red[w];
        mu_sh = s * (1.f / C_S);
    }
    __syncthreads();
    float mu = mu_sh;
    float d  = v - mu;

    // var
    x = d * d;
    #pragma unroll
    for (int o = 16; o; o >>= 1) x += __shfl_xor_sync(0xffffffffu, x, o);
    if ((t & 31) == 0) red[t >> 5] = x;
    __syncthreads();
    if (t == 0) {
        float s = 0.f;
        #pragma unroll
        for (int w = 0; w < 8; w++) s += red[w];
        rstd_sh = rsqrtf(s * (1.f / C_S) + LN_EPS);
    }
    __syncthreads();

    float uu = d * rstd_sh * ln_w[t] + ln_b[t];
    g_u[i * C_S + t] = uu;
    u_s[t] = uu;
    __syncthreads();

    // zjb[i, z] = sum_c u[i,c] * W2[c,z] + b_pair[z]   (W2 = rows [C_S, 2*C_S))
    if (t < C_Z) {
        float acc = b_pair[t];
        #pragma unroll 8
        for (int c = 0; c < C_S; c++)
            acc += u_s[c] * W_pair[(C_S + c) * C_Z + t];
        g_zjb[i * C_Z + t] = acc;
    }
}

// ---------------------------------------------------------------------------
// Kernel 2: per (i-tile of 128, j): D[128,128] = U_tile[128,256] @ B[256,128]
// where B[c,z] = u[j,c]*W3[c,z] + W1[c,z]   (folds zi into the GEMM).
// Epilogue adds zjb[j,:] + E_chainpair + E_relpos and stores z.
// All FMA work as packed fma.rn.f32x2 (needed to hit 128 FMA/cyc/SM).
// ---------------------------------------------------------------------------
#define BM 128
#define BN 128
#define BK 32

__global__ __launch_bounds__(256, 2)
void pair_kernel(const int* __restrict__ chain,
                 const int* __restrict__ ridx,
                 const float* __restrict__ E_cp,   // (4,   C_Z)
                 const float* __restrict__ E_rp,   // (66,  C_Z)
                 const float* __restrict__ W_pair, // (768, C_Z)
                 float* __restrict__ out_z)        // (L, L, C_Z)
{
    __shared__ float As[BK][BM];      // transposed: As[c][i]
    __shared__ float Bs[BK][BN];      // Bs[c][z]
    __shared__ int   chain_s[BM];
    __shared__ int   ridx_s[BM];
    __shared__ float zjb_s[C_Z];

    const int t  = threadIdx.x;       // 256 threads
    const int j  = blockIdx.x;        // 0..511
    const int i0 = blockIdx.y * BM;   // 0,128,256,384

    if (t < BM) {
        chain_s[t] = chain[i0 + t];
        ridx_s[t]  = ridx[i0 + t];
    }
    if (t < C_Z) zjb_s[t] = g_zjb[j * C_Z + t];

    const int cj = chain[j];
    const int rj = ridx[j];

    const int tx = t & 15;            // z-tile:  columns tx*8 .. tx*8+7
    const int ty = t >> 4;            // i-tile:  rows    ty*8 .. ty*8+7

    unsigned long long acc[8][4];     // 8 rows x 4 f32x2 z-pairs
    #pragma unroll
    for (int r = 0; r < 8; r++)
        #pragma unroll
        for (int p = 0; p < 4; p++) acc[r][p] = 0ull;

    const int arow = t >> 1;              // A load: row, then 16 cols
    const int acb  = (t & 1) * 16;
    const int bk   = t >> 3;              // B build: c index within chunk
    const int bzb  = (t & 7) * 16;        // 16 consecutive z

    for (int kc = 0; kc < C_S; kc += BK) {
        // ---- load A chunk (coalesced), store transposed ----
        const float4* gA = (const float4*)(g_u + (size_t)(i0 + arow) * C_S + kc + acb);
        #pragma unroll
        for (int q = 0; q < 4; q++) {
            float4 v = gA[q];
            int c = acb + q * 4;
            As[c + 0][arow] = v.x;
            As[c + 1][arow] = v.y;
            As[c + 2][arow] = v.z;
            As[c + 3][arow] = v.w;
        }
        // ---- build B chunk: B[c,z] = u[j,c]*W3[c,z] + W1[c,z] ----
        {
            int c = kc + bk;
            float ujc = g_u[j * C_S + c];
            const float4* w3 = (const float4*)(W_pair + (size_t)(2 * C_S + c) * C_Z + bzb);
            const float4* w1 = (const float4*)(W_pair + (size_t)c * C_Z + bzb);
            #pragma unroll
            for (int q = 0; q < 4; q++) {
                float4 a = w3[q], b = w1[q];
                float4 o;
                o.x = fmaf(ujc, a.x, b.x);
                o.y = fmaf(ujc, a.y, b.y);
                o.z = fmaf(ujc, a.z, b.z);
                o.w = fmaf(ujc, a.w, b.w);
                *(float4*)&Bs[bk][bzb + q * 4] = o;
            }
        }
        __syncthreads();

        #pragma unroll 8
        for (int k = 0; k < BK; k++) {
            float a[8];
            *(float4*)(a + 0) = *(const float4*)&As[k][ty * 8];
            *(float4*)(a + 4) = *(const float4*)&As[k][ty * 8 + 4];
            unsigned long long b[4];
            const unsigned long long* pb =
                (const unsigned long long*)&Bs[k][tx * 8];
            b[0] = pb[0]; b[1] = pb[1]; b[2] = pb[2]; b[3] = pb[3];
            #pragma unroll
            for (int r = 0; r < 8; r++) {
                unsigned long long ap;
                asm("mov.b64 %0, {%1, %2};" : "=l"(ap) : "f"(a[r]), "f"(a[r]));
                #pragma unroll
                for (int p = 0; p < 4; p++)
                    asm("fma.rn.f32x2 %0, %1, %2, %0;"
                        : "+l"(acc[r][p]) : "l"(ap), "l"(b[p]));
            }
        }
        __syncthreads();
    }

    // ---- epilogue ----
    float zb[8];
    *(float4*)(zb + 0) = *(const float4*)&zjb_s[tx * 8];
    *(float4*)(zb + 4) = *(const float4*)&zjb_s[tx * 8 + 4];

    #pragma unroll
    for (int r = 0; r < 8; r++) {
        int il = ty * 8 + r;
        int irow = i0 + il;
        int ci = chain_s[il], ri = ridx_s[il];
        int cp = ci * 2 + cj;
        int dd = ri - rj;
        int dcl = dd < -32 ? -32 : (dd > 32 ? 32 : dd);
        int rp = (ci == cj) ? (dcl + 32) : 65;

        const float4* ecp = (const float4*)(E_cp + (size_t)cp * C_Z + tx * 8);
        const float4* erp = (const float4*)(E_rp + (size_t)rp * C_Z + tx * 8);
        float4 e0 = ecp[0], e1 = ecp[1];
        float4 p0 = erp[0], p1 = erp[1];

        float lo, hi;
        float4 o0, o1;
        asm("mov.b64 {%0, %1}, %2;" : "=f"(lo), "=f"(hi) : "l"(acc[r][0]));
        o0.x = lo + zb[0] + e0.x + p0.x;
        o0.y = hi + zb[1] + e0.y + p0.y;
        asm("mov.b64 {%0, %1}, %2;" : "=f"(lo), "=f"(hi) : "l"(acc[r][1]));
        o0.z = lo + zb[2] + e0.z + p0.z;
        o0.w = hi + zb[3] + e0.w + p0.w;
        asm("mov.b64 {%0, %1}, %2;" : "=f"(lo), "=f"(hi) : "l"(acc[r][2]));
        o1.x = lo + zb[4] + e1.x + p1.x;
        o1.y = hi + zb[5] + e1.y + p1.y;
        asm("mov.b64 {%0, %1}, %2;" : "=f"(lo), "=f"(hi) : "l"(acc[r][3]));
        o1.z = lo + zb[6] + e1.z + p1.z;
        o1.w = hi + zb[7] + e1.w + p1.w;

        float* outp = out_z + ((size_t)irow * L_RES + j) * C_Z + tx * 8;
        *(float4*)(outp + 0) = o0;
        *(float4*)(outp + 4) = o1;
    }
}

// ---------------------------------------------------------------------------
extern "C" void kernel_launch(void* const* d_in, const int* in_sizes, int n_in,
                              void* d_out, int out_size)
{
    const int*   seq     = (const int*)  d_in[0];
    const int*   chain   = (const int*)  d_in[1];
    const int*   ridx    = (const int*)  d_in[2];
    const float* E_aa    = (const float*)d_in[3];
    const float* E_pos   = (const float*)d_in[4];
    const float* E_chain = (const float*)d_in[5];
    const float* E_cp    = (const float*)d_in[6];
    const float* E_rp    = (const float*)d_in[7];
    const float* W_pair  = (const float*)d_in[8];
    const float* b_pair  = (const float*)d_in[9];
    const float* ln_w    = (const float*)d_in[10];
    const float* ln_b    = (const float*)d_in[11];

    float* out_s = (float*)d_out;
    float* out_z = out_s + (size_t)L_RES * C_S;

    prep_kernel<<<L_RES, C_S>>>(seq, chain, ridx, E_aa, E_pos, E_chain,
                                W_pair, b_pair, ln_w, ln_b, out_s);
    pair_kernel<<<dim3(L_RES, L_RES / BM), 256>>>(chain, ridx, E_cp, E_rp,
                                                  W_pair, out_z);
}